// round 9
// baseline (speedup 1.0000x reference)
#include <cuda_runtime.h>
#include <cstdint>
#include <cstddef>

#define B_TOTAL 65536
#define NGRAPH  64
#define NNODES  2048
#define NEDGES  16384
#define META    64
#define TXD     8
#define NOISE   128
#define RROWS   64     // rows per block in main kernel
#define KPAD    48     // 41 features padded to 6 k-steps of 8
#define TDS     72     // td_s row stride (floats)
#define FS      68     // feat_s row stride (floats)
#define WS      136    // Wt_s row stride (floats)  (136 % 32 == 8 -> conflict-free B)
#define ESPLIT  8
#define GK      64     // gcn_gemm K-splits (32 rows each)
#define GROWS   32

typedef unsigned long long ull;

// Fused zero-init scratch: [deg_all | agg_all | g_go]
#define SCRATCH_FLOATS (NGRAPH * NNODES * 2 + NGRAPH * NOISE)   // 270336
__device__ float scratch[SCRATCH_FLOATS];
#define DEG_ALL (scratch)
#define AGG_ALL (scratch + NGRAPH * NNODES)
#define G_GO    (scratch + 2 * NGRAPH * NNODES)

// ---------- PDL ----------
__device__ __forceinline__ void pdl_wait() {
    asm volatile("griddepcontrol.wait;" ::: "memory");
}

// ---------- helpers ----------
__device__ __forceinline__ ull pack2(float lo, float hi) {
    ull r; asm("mov.b64 %0, {%1,%2};" : "=l"(r) : "f"(lo), "f"(hi)); return r;
}
__device__ __forceinline__ ull fma2(ull a, ull b, ull c) {
    ull d; asm("fma.rn.f32x2 %0, %1, %2, %3;" : "=l"(d) : "l"(a), "l"(b), "l"(c)); return d;
}
__device__ __forceinline__ void unpack2(ull v, float& lo, float& hi) {
    asm("mov.b64 {%0,%1}, %2;" : "=f"(lo), "=f"(hi) : "l"(v));
}
__device__ __forceinline__ float to_tf32(float x) {
    uint32_t u; asm("cvt.rna.tf32.f32 %0, %1;" : "=r"(u) : "f"(x));
    return __uint_as_float(u);
}
__device__ __forceinline__ void stcs2(float* p, float a, float b) {
    asm volatile("st.global.cs.v2.f32 [%0], {%1,%2};"
                 :: "l"(p), "f"(a), "f"(b) : "memory");
}
__device__ __forceinline__ void mma_tf32(
    float& c0, float& c1, float& c2, float& c3,
    uint32_t a0, uint32_t a1, uint32_t a2, uint32_t a3,
    uint32_t b0, uint32_t b1)
{
    asm volatile(
        "mma.sync.aligned.m16n8k8.row.col.f32.tf32.tf32.f32 "
        "{%0,%1,%2,%3}, {%4,%5,%6,%7}, {%8,%9}, {%0,%1,%2,%3};"
        : "+f"(c0), "+f"(c1), "+f"(c2), "+f"(c3)
        : "r"(a0), "r"(a1), "r"(a2), "r"(a3), "r"(b0), "r"(b1));
}

// ============================================================================
// k_zero / k_deg / k_norm / gcn_gemm — unchanged from R8 (PDL chain)
// ============================================================================
__global__ __launch_bounds__(256) void k_zero() {
    reinterpret_cast<float4*>(scratch)[blockIdx.x * 256 + threadIdx.x] =
        make_float4(0.f, 0.f, 0.f, 0.f);
}

__global__ __launch_bounds__(256) void k_deg(const int* __restrict__ edges) {
    const int g  = blockIdx.x >> 3;
    const int sp = blockIdx.x & 7;
    const int4* dst4 = reinterpret_cast<const int4*>(
        edges + (size_t)g * 2 * NEDGES + NEDGES) + sp * (NEDGES / ESPLIT / 4);
    int4 d0 = __ldg(&dst4[threadIdx.x]);
    int4 d1 = __ldg(&dst4[256 + threadIdx.x]);
    pdl_wait();
    float* deg = DEG_ALL + (size_t)g * NNODES;
    atomicAdd(&deg[d0.x], 1.0f);
    atomicAdd(&deg[d0.y], 1.0f);
    atomicAdd(&deg[d0.z], 1.0f);
    atomicAdd(&deg[d0.w], 1.0f);
    atomicAdd(&deg[d1.x], 1.0f);
    atomicAdd(&deg[d1.y], 1.0f);
    atomicAdd(&deg[d1.z], 1.0f);
    atomicAdd(&deg[d1.w], 1.0f);
}

__global__ __launch_bounds__(256) void k_norm(const int* __restrict__ edges) {
    __shared__ float dinv_s[NNODES];
    const int g  = blockIdx.x >> 3;
    const int sp = blockIdx.x & 7;
    const int tid = threadIdx.x;
    const int* base = edges + (size_t)g * 2 * NEDGES;
    const int4* src4 = reinterpret_cast<const int4*>(base) + sp * (NEDGES / ESPLIT / 4);
    const int4* dst4 = reinterpret_cast<const int4*>(base + NEDGES) + sp * (NEDGES / ESPLIT / 4);
    int4 s0 = __ldg(&src4[tid]);
    int4 s1 = __ldg(&src4[256 + tid]);
    int4 d0 = __ldg(&dst4[tid]);
    int4 d1 = __ldg(&dst4[256 + tid]);
    pdl_wait();
    const float* deg = DEG_ALL + (size_t)g * NNODES;
    #pragma unroll
    for (int i = 0; i < NNODES / 256; i++)
        dinv_s[i * 256 + tid] = rsqrtf(deg[i * 256 + tid] + 1.0f);
    __syncthreads();
    float* agg = AGG_ALL + (size_t)g * NNODES;
    atomicAdd(&agg[d0.x], dinv_s[s0.x] * dinv_s[d0.x]);
    atomicAdd(&agg[d0.y], dinv_s[s0.y] * dinv_s[d0.y]);
    atomicAdd(&agg[d0.z], dinv_s[s0.z] * dinv_s[d0.z]);
    atomicAdd(&agg[d0.w], dinv_s[s0.w] * dinv_s[d0.w]);
    atomicAdd(&agg[d1.x], dinv_s[s1.x] * dinv_s[d1.x]);
    atomicAdd(&agg[d1.y], dinv_s[s1.y] * dinv_s[d1.y]);
    atomicAdd(&agg[d1.z], dinv_s[s1.z] * dinv_s[d1.z]);
    atomicAdd(&agg[d1.w], dinv_s[s1.w] * dinv_s[d1.w]);
}

__global__ __launch_bounds__(128) void gcn_gemm(
    const float* __restrict__ embW, const float* __restrict__ gwp,
    const float* __restrict__ gbp)
{
    __shared__ float aggs[8][GROWS];
    const int tid = threadIdx.x;
    const int ks  = blockIdx.x & (GK - 1);
    const int gsp = blockIdx.x >> 6;

    const float* wb = embW + (size_t)ks * GROWS * NOISE + tid;
    float wsum = 0.f;
    #pragma unroll
    for (int n = 0; n < GROWS; n++)
        wsum += __ldg(wb + (size_t)n * NOISE);

    pdl_wait();

    for (int t = tid; t < 8 * GROWS; t += 128) {
        int j = t >> 5, n = t & (GROWS - 1);
        size_t idx = (size_t)(gsp * 8 + j) * NNODES + ks * GROWS + n;
        float r = rsqrtf(DEG_ALL[idx] + 1.0f);
        aggs[j][n] = AGG_ALL[idx] + r * r;
    }
    __syncthreads();

    float acc[8] = {0.f, 0.f, 0.f, 0.f, 0.f, 0.f, 0.f, 0.f};
    #pragma unroll
    for (int n = 0; n < GROWS; n++) {
        float wv = __ldg(wb + (size_t)n * NOISE);
        #pragma unroll
        for (int j = 0; j < 8; j++)
            acc[j] = fmaf(aggs[j][n], wv, acc[j]);
    }
    const float w = gwp[0], b = gbp[0];
    const float bterm = b * wsum;
    #pragma unroll
    for (int j = 0; j < 8; j++)
        atomicAdd(&G_GO[(gsp * 8 + j) * NOISE + tid], fmaf(w, acc[j], bterm));
}

// ============================================================================
// noise_main: phase 1 = f32x2 trig MLP (pre-wait, overlaps GCN chain);
// phase 2 = tf32 mma.sync GEMM over 48 padded features, C init from g_go.
// 128 threads, 64 rows/block. Warp w: rows 16w..16w+15, all 16 n-tiles.
// ============================================================================
__global__ __launch_bounds__(128, 6) void noise_main(
    const int*   __restrict__ gid,   const float* __restrict__ chain,
    const float* __restrict__ td,    const float* __restrict__ tx,
    const float* __restrict__ trigW, const float* __restrict__ trigb,
    const float* __restrict__ embW,  const float* __restrict__ embb,
    float* __restrict__ out)
{
    // Union: td_s (64 x TDS, phase 1 input) then Wt_s (48 x WS, phase 2 B)
    __shared__ __align__(16) float uni[KPAD * WS];      // 6528 floats
    __shared__ __align__(16) float feat[KPAD * FS];     // 3264 floats
    __shared__ float embb_s[NOISE];
    __shared__ int gs[RROWS];

    const int tid  = threadIdx.x;
    const int r0   = blockIdx.x * RROWS;
    const int lane = tid & 31;
    const int w    = tid >> 5;

    // ---- stage td (transposed, rotated), tx, chain, feat zero-pad ----
    {
        const float4* tdg = reinterpret_cast<const float4*>(td + (size_t)r0 * META);
        #pragma unroll
        for (int it = 0; it < 8; it++) {
            int i = it * 128 + tid;
            int r = i >> 4;           // row 0..63
            int q = i & 15;           // m-quad
            float4 v = tdg[i];
            float vv[4] = {v.x, v.y, v.z, v.w};
            #pragma unroll
            for (int j = 0; j < 4; j++) {
                int c = ((q >> 1) + j) & 3;
                uni[(4 * q + c) * TDS + r] = vv[c];
            }
        }
        {   // tx -> feat rows 33..40 (tf32-rounded)
            const float4* txg = reinterpret_cast<const float4*>(tx + (size_t)r0 * TXD);
            int r = tid >> 1, q = tid & 1;
            float4 v = txg[tid];
            feat[(33 + 4 * q + 0) * FS + r] = to_tf32(v.x);
            feat[(33 + 4 * q + 1) * FS + r] = to_tf32(v.y);
            feat[(33 + 4 * q + 2) * FS + r] = to_tf32(v.z);
            feat[(33 + 4 * q + 3) * FS + r] = to_tf32(v.w);
        }
        if (tid < RROWS) {
            feat[0 * FS + tid] = to_tf32(chain[r0 + tid]);
            gs[tid] = gid[r0 + tid];
        }
        for (int t = tid; t < (KPAD - 41) * FS; t += 128)   // zero pad rows 41..47
            feat[41 * FS + t] = 0.f;
    }
    __syncthreads();

    // ---- phase 1: trig = relu(td @ trig_W + trig_b), 8 pairs/warp ----
    {
        const int k = lane;
        float tb = __ldg(&trigb[k]);
        ull acc[8];
        #pragma unroll
        for (int u = 0; u < 8; u++) acc[u] = pack2(tb, tb);
        #pragma unroll 8
        for (int m = 0; m < META; m++) {
            float wv = __ldg(&trigW[m * 32 + k]);
            ull wd = pack2(wv, wv);
            const float* tr = &uni[m * TDS + 16 * w];
            ulonglong2 t0 = *reinterpret_cast<const ulonglong2*>(tr);
            ulonglong2 t1 = *reinterpret_cast<const ulonglong2*>(tr + 4);
            ulonglong2 t2 = *reinterpret_cast<const ulonglong2*>(tr + 8);
            ulonglong2 t3 = *reinterpret_cast<const ulonglong2*>(tr + 12);
            acc[0] = fma2(wd, t0.x, acc[0]);
            acc[1] = fma2(wd, t0.y, acc[1]);
            acc[2] = fma2(wd, t1.x, acc[2]);
            acc[3] = fma2(wd, t1.y, acc[3]);
            acc[4] = fma2(wd, t2.x, acc[4]);
            acc[5] = fma2(wd, t2.y, acc[5]);
            acc[6] = fma2(wd, t3.x, acc[6]);
            acc[7] = fma2(wd, t3.y, acc[7]);
        }
        #pragma unroll
        for (int u = 0; u < 8; u++) {
            float a, b2;
            unpack2(acc[u], a, b2);
            *reinterpret_cast<ull*>(&feat[(1 + k) * FS + 16 * w + 2 * u]) =
                pack2(to_tf32(fmaxf(a, 0.f)), to_tf32(fmaxf(b2, 0.f)));
        }
    }
    __syncthreads();   // td_s dead; feat complete

    // ---- stage Wt (48 x 136, tf32-rounded) + embb into smem ----
    for (int t = tid; t < 41 * NOISE; t += 128) {
        int row = t >> 7, col = t & (NOISE - 1);
        uni[row * WS + col] = to_tf32(__ldg(&embW[(size_t)(2048 + row) * NOISE + col]));
    }
    for (int t = tid; t < (KPAD - 41) * WS; t += 128)
        uni[41 * WS + t] = 0.f;
    embb_s[tid] = embb[tid];

    // ---- A fragments (feat is ready; overlaps Wt staging latency) ----
    const int g = lane >> 2;      // 0..7
    const int t4 = lane & 3;      // 0..3
    const int rb0 = 16 * w;
    uint32_t A[6][4];
    #pragma unroll
    for (int ks = 0; ks < 6; ks++) {
        A[ks][0] = __float_as_uint(feat[(8 * ks + t4) * FS + rb0 + g]);
        A[ks][1] = __float_as_uint(feat[(8 * ks + t4) * FS + rb0 + g + 8]);
        A[ks][2] = __float_as_uint(feat[(8 * ks + t4 + 4) * FS + rb0 + g]);
        A[ks][3] = __float_as_uint(feat[(8 * ks + t4 + 4) * FS + rb0 + g + 8]);
    }
    __syncthreads();   // Wt_s complete

    pdl_wait();        // g_go complete

    // ---- phase 2: 16 n-tiles of m16n8k8 tf32 mma, C init from g_go ----
    {
        const int lrA = rb0 + g, lrB = lrA + 8;
        const float* gA = &G_GO[gs[lrA] * NOISE];
        const float* gB = &G_GO[gs[lrB] * NOISE];
        float* outA = out + (size_t)(r0 + lrA) * NOISE;
        float* outB = out + (size_t)(r0 + lrB) * NOISE;

        #pragma unroll
        for (int nt = 0; nt < 16; nt++) {
            const int cb = nt * 8 + 2 * t4;
            float2 ga = __ldg(reinterpret_cast<const float2*>(gA + cb));
            float2 gb = __ldg(reinterpret_cast<const float2*>(gB + cb));
            float2 eb = *reinterpret_cast<const float2*>(&embb_s[cb]);
            float c0 = ga.x + eb.x, c1 = ga.y + eb.y;
            float c2 = gb.x + eb.x, c3 = gb.y + eb.y;

            #pragma unroll
            for (int ks = 0; ks < 6; ks++) {
                uint32_t b0 = __float_as_uint(uni[(8 * ks + t4) * WS + nt * 8 + g]);
                uint32_t b1 = __float_as_uint(uni[(8 * ks + t4 + 4) * WS + nt * 8 + g]);
                mma_tf32(c0, c1, c2, c3,
                         A[ks][0], A[ks][1], A[ks][2], A[ks][3], b0, b1);
            }
            stcs2(outA + cb, c0, c1);
            stcs2(outB + cb, c2, c3);
        }
    }
}

// ============================================================================
extern "C" void kernel_launch(void* const* d_in, const int* in_sizes, int n_in,
                              void* d_out, int out_size) {
    (void)in_sizes; (void)n_in; (void)out_size;
    const int*   gid   = (const int*)  d_in[0];
    const float* chain = (const float*)d_in[1];
    const float* td    = (const float*)d_in[2];
    const float* tx    = (const float*)d_in[3];
    const int*   edges = (const int*)  d_in[4];
    const float* gw    = (const float*)d_in[5];
    const float* gb    = (const float*)d_in[6];
    const float* trigW = (const float*)d_in[7];
    const float* trigb = (const float*)d_in[8];
    const float* embW  = (const float*)d_in[9];
    const float* embb  = (const float*)d_in[10];
    float* out = (float*)d_out;

    cudaLaunchAttribute pattr;
    pattr.id = cudaLaunchAttributeProgrammaticStreamSerialization;
    pattr.val.programmaticStreamSerializationAllowed = 1;

    k_zero<<<SCRATCH_FLOATS / 4 / 256, 256>>>();

    cudaLaunchConfig_t cfg = {};
    cfg.blockDim = dim3(256, 1, 1);
    cfg.stream   = 0;
    cfg.attrs    = &pattr;
    cfg.numAttrs = 1;

    cfg.gridDim = dim3(NGRAPH * ESPLIT, 1, 1);
    cudaLaunchKernelEx(&cfg, k_deg, edges);

    cfg.gridDim = dim3(NGRAPH * ESPLIT, 1, 1);
    cudaLaunchKernelEx(&cfg, k_norm, edges);

    cfg.blockDim = dim3(128, 1, 1);
    cfg.gridDim  = dim3(GK * 8, 1, 1);
    cudaLaunchKernelEx(&cfg, gcn_gemm, embW, gw, gb);

    cfg.gridDim = dim3(B_TOTAL / RROWS, 1, 1);
    cudaLaunchKernelEx(&cfg, noise_main, gid, chain, td, tx, trigW, trigb,
                       embW, embb, out);
}

// round 10
// speedup vs baseline: 1.1942x; 1.1942x over previous
#include <cuda_runtime.h>
#include <cstdint>
#include <cstddef>

#define B_TOTAL 65536
#define NGRAPH  64
#define NNODES  2048
#define NEDGES  16384
#define META    64
#define TXD     8
#define NOISE   128
#define RROWS   32    // rows per block in main kernel (16 row-pairs, 4/warp)
#define NFEAT   41    // chain(1) + trig(32) + tx(8)
#define SPAD    36    // padded row stride (floats)
#define ESPLIT  8     // edge splits per graph
#define GK      128   // gcn_gemm K-splits
#define GROWS   16    // rows per gcn_gemm block

typedef unsigned long long ull;

// Fused zero-init scratch: [deg_all | agg_all | g_go]
#define SCRATCH_FLOATS (NGRAPH * NNODES * 2 + NGRAPH * NOISE)   // 270336
__device__ float scratch[SCRATCH_FLOATS];
#define DEG_ALL (scratch)
#define AGG_ALL (scratch + NGRAPH * NNODES)
#define G_GO    (scratch + 2 * NGRAPH * NNODES)

// ---------- PDL ----------
__device__ __forceinline__ void pdl_wait() {
    asm volatile("griddepcontrol.wait;" ::: "memory");
}

// ---------- f32x2 helpers ----------
__device__ __forceinline__ ull pack2(float lo, float hi) {
    ull r; asm("mov.b64 %0, {%1,%2};" : "=l"(r) : "f"(lo), "f"(hi)); return r;
}
__device__ __forceinline__ ull fma2(ull a, ull b, ull c) {
    ull d; asm("fma.rn.f32x2 %0, %1, %2, %3;" : "=l"(d) : "l"(a), "l"(b), "l"(c)); return d;
}
__device__ __forceinline__ void unpack2(ull v, float& lo, float& hi) {
    asm("mov.b64 {%0,%1}, %2;" : "=f"(lo), "=f"(hi) : "l"(v));
}
__device__ __forceinline__ void stcs4(float* p, float4 v) {
    asm volatile("st.global.cs.v4.f32 [%0], {%1,%2,%3,%4};"
                 :: "l"(p), "f"(v.x), "f"(v.y), "f"(v.z), "f"(v.w) : "memory");
}

// ============================================================================
// k_zero: zero the fused scratch block (PDL-chain member).
// ============================================================================
__global__ __launch_bounds__(256) void k_zero() {
    reinterpret_cast<float4*>(scratch)[blockIdx.x * 256 + threadIdx.x] =
        make_float4(0.f, 0.f, 0.f, 0.f);
}

// ============================================================================
// k_deg: edge loads (prologue, overlaps k_zero) -> wait -> REDG counts.
// ============================================================================
__global__ __launch_bounds__(256) void k_deg(const int* __restrict__ edges) {
    const int g  = blockIdx.x >> 3;
    const int sp = blockIdx.x & 7;
    const int4* dst4 = reinterpret_cast<const int4*>(
        edges + (size_t)g * 2 * NEDGES + NEDGES) + sp * (NEDGES / ESPLIT / 4);
    int4 d0 = __ldg(&dst4[threadIdx.x]);
    int4 d1 = __ldg(&dst4[256 + threadIdx.x]);

    pdl_wait();   // scratch must be zeroed

    float* deg = DEG_ALL + (size_t)g * NNODES;
    atomicAdd(&deg[d0.x], 1.0f);
    atomicAdd(&deg[d0.y], 1.0f);
    atomicAdd(&deg[d0.z], 1.0f);
    atomicAdd(&deg[d0.w], 1.0f);
    atomicAdd(&deg[d1.x], 1.0f);
    atomicAdd(&deg[d1.y], 1.0f);
    atomicAdd(&deg[d1.z], 1.0f);
    atomicAdd(&deg[d1.w], 1.0f);
}

// ============================================================================
// k_norm: edge loads (prologue, overlaps k_deg) -> wait -> smem dinv stage ->
// agg[dst] += dinv[src]*dinv[dst] via REDG.
// ============================================================================
__global__ __launch_bounds__(256) void k_norm(const int* __restrict__ edges) {
    __shared__ float dinv_s[NNODES];
    const int g  = blockIdx.x >> 3;
    const int sp = blockIdx.x & 7;
    const int tid = threadIdx.x;

    const int* base = edges + (size_t)g * 2 * NEDGES;
    const int4* src4 = reinterpret_cast<const int4*>(base) + sp * (NEDGES / ESPLIT / 4);
    const int4* dst4 = reinterpret_cast<const int4*>(base + NEDGES) + sp * (NEDGES / ESPLIT / 4);
    int4 s0 = __ldg(&src4[tid]);
    int4 s1 = __ldg(&src4[256 + tid]);
    int4 d0 = __ldg(&dst4[tid]);
    int4 d1 = __ldg(&dst4[256 + tid]);

    pdl_wait();   // deg must be complete

    const float* deg = DEG_ALL + (size_t)g * NNODES;
    #pragma unroll
    for (int i = 0; i < NNODES / 256; i++)
        dinv_s[i * 256 + tid] = rsqrtf(deg[i * 256 + tid] + 1.0f);
    __syncthreads();

    float* agg = AGG_ALL + (size_t)g * NNODES;
    atomicAdd(&agg[d0.x], dinv_s[s0.x] * dinv_s[d0.x]);
    atomicAdd(&agg[d0.y], dinv_s[s0.y] * dinv_s[d0.y]);
    atomicAdd(&agg[d0.z], dinv_s[s0.z] * dinv_s[d0.z]);
    atomicAdd(&agg[d0.w], dinv_s[s0.w] * dinv_s[d0.w]);
    atomicAdd(&agg[d1.x], dinv_s[s1.x] * dinv_s[d1.x]);
    atomicAdd(&agg[d1.y], dinv_s[s1.y] * dinv_s[d1.y]);
    atomicAdd(&agg[d1.z], dinv_s[s1.z] * dinv_s[d1.z]);
    atomicAdd(&agg[d1.w], dinv_s[s1.w] * dinv_s[d1.w]);
}

// ============================================================================
// gcn_gemm: 1024 blocks = 128 K-splits (16 rows) x 8 graph-groups (8 graphs).
// Pass A (pre-wait): wsum over slice + warm cache. Wait. Pass B: 16x8 FMA.
// g_go += w * ((AGG + dinv^2) @ embW_slice) + b * colsum(embW_slice)
// ============================================================================
__global__ __launch_bounds__(128) void gcn_gemm(
    const float* __restrict__ embW, const float* __restrict__ gwp,
    const float* __restrict__ gbp)
{
    __shared__ float aggs[8][GROWS];
    const int tid = threadIdx.x;
    const int ks  = blockIdx.x & (GK - 1);   // K slice of GROWS rows
    const int gsp = blockIdx.x >> 7;         // graph group (8 graphs)

    // pass A: wsum over the slice column (independent of GCN chain)
    const float* wb = embW + (size_t)ks * GROWS * NOISE + tid;
    float wsum = 0.f;
    #pragma unroll
    for (int n = 0; n < GROWS; n++)
        wsum += __ldg(wb + (size_t)n * NOISE);

    pdl_wait();   // agg must be complete

    if (tid < 8 * GROWS) {
        int j = tid >> 4, n = tid & (GROWS - 1);
        size_t idx = (size_t)(gsp * 8 + j) * NNODES + ks * GROWS + n;
        float r = rsqrtf(DEG_ALL[idx] + 1.0f);
        aggs[j][n] = AGG_ALL[idx] + r * r;
    }
    __syncthreads();

    float acc[8] = {0.f, 0.f, 0.f, 0.f, 0.f, 0.f, 0.f, 0.f};
    #pragma unroll
    for (int n = 0; n < GROWS; n++) {
        float wv = __ldg(wb + (size_t)n * NOISE);
        #pragma unroll
        for (int j = 0; j < 8; j++)
            acc[j] = fmaf(aggs[j][n], wv, acc[j]);
    }
    const float w = gwp[0], b = gbp[0];
    const float bterm = b * wsum;
    #pragma unroll
    for (int j = 0; j < 8; j++)
        atomicAdd(&G_GO[(gsp * 8 + j) * NOISE + tid], fmaf(w, acc[j], bterm));
}

// ============================================================================
// noise_main (R8-proven): staging + trig MLP PRE-wait; wait; g_go gather +
// f32x2 output GEMM. 128 threads, 32 rows/block.
// ============================================================================
__global__ __launch_bounds__(128, 5) void noise_main(
    const int*   __restrict__ gid,   const float* __restrict__ chain,
    const float* __restrict__ td,    const float* __restrict__ tx,
    const float* __restrict__ trigW, const float* __restrict__ trigb,
    const float* __restrict__ embW,  const float* __restrict__ embb,
    float* __restrict__ out)
{
    __shared__ __align__(16) float td_s[META][SPAD];
    __shared__ __align__(16) float feat_s[NFEAT][SPAD];  // 0=chain,1..32=trig,33..40=tx
    __shared__ int gs[RROWS];

    const int tid = threadIdx.x;
    const int r0  = blockIdx.x * RROWS;
    const int lane = tid & 31;
    const int w    = tid >> 5;

    // ---- stage inputs (transposed; rotated components -> 2-way conflicts) ----
    {
        const float4* tdg = reinterpret_cast<const float4*>(td + (size_t)r0 * META);
        #pragma unroll
        for (int it = 0; it < 4; it++) {
            int i = it * 128 + tid;
            int r = i >> 4;           // row 0..31
            int q = i & 15;           // m-quad
            float4 v = tdg[i];        // coalesced
            float vv[4] = {v.x, v.y, v.z, v.w};
            #pragma unroll
            for (int j = 0; j < 4; j++) {
                int c = ((q >> 1) + j) & 3;
                td_s[4 * q + c][r] = vv[c];
            }
        }
        if (tid < 64) {
            const float4* txg = reinterpret_cast<const float4*>(tx + (size_t)r0 * TXD);
            int r = tid >> 1, q = tid & 1;
            float4 v = txg[tid];
            feat_s[33 + 4 * q + 0][r] = v.x;
            feat_s[33 + 4 * q + 1][r] = v.y;
            feat_s[33 + 4 * q + 2][r] = v.z;
            feat_s[33 + 4 * q + 3][r] = v.w;
        }
        if (tid < RROWS) {
            feat_s[0][tid] = chain[r0 + tid];
            gs[tid] = gid[r0 + tid];
        }
    }
    __syncthreads();

    // ---- phase 1: trig = relu(td @ trig_W + trig_b), 4 pairs/warp ----
    {
        const int k = lane;                    // output feature
        float tb = __ldg(&trigb[k]);
        ull acc0 = pack2(tb, tb), acc1 = acc0, acc2 = acc0, acc3 = acc0;
        #pragma unroll 8
        for (int m = 0; m < META; m++) {
            float wv = __ldg(&trigW[m * 32 + k]);
            ull wd = pack2(wv, wv);
            ulonglong2 t01 = *reinterpret_cast<const ulonglong2*>(&td_s[m][8 * w]);
            ulonglong2 t23 = *reinterpret_cast<const ulonglong2*>(&td_s[m][8 * w + 4]);
            acc0 = fma2(wd, t01.x, acc0);
            acc1 = fma2(wd, t01.y, acc1);
            acc2 = fma2(wd, t23.x, acc2);
            acc3 = fma2(wd, t23.y, acc3);
        }
        float a, b2;
        unpack2(acc0, a, b2);
        *reinterpret_cast<ull*>(&feat_s[1 + k][8 * w + 0]) = pack2(fmaxf(a, 0.f), fmaxf(b2, 0.f));
        unpack2(acc1, a, b2);
        *reinterpret_cast<ull*>(&feat_s[1 + k][8 * w + 2]) = pack2(fmaxf(a, 0.f), fmaxf(b2, 0.f));
        unpack2(acc2, a, b2);
        *reinterpret_cast<ull*>(&feat_s[1 + k][8 * w + 4]) = pack2(fmaxf(a, 0.f), fmaxf(b2, 0.f));
        unpack2(acc3, a, b2);
        *reinterpret_cast<ull*>(&feat_s[1 + k][8 * w + 6]) = pack2(fmaxf(a, 0.f), fmaxf(b2, 0.f));
    }
    __syncthreads();

    pdl_wait();   // g_go must be complete from here on

    // ---- phase 2: output GEMM over 41 features, 4 pairs x 4 cols / thread ----
    {
        const int jq = lane;                   // cols 4*jq..4*jq+3
        const float4 eb = __ldg(reinterpret_cast<const float4*>(&embb[4 * jq]));

        float4 preA[4], preB[4];
        #pragma unroll
        for (int u = 0; u < 4; u++) {
            int ra = 8 * w + 2 * u, rb = ra + 1;
            preA[u] = __ldg(reinterpret_cast<const float4*>(&G_GO[gs[ra] * NOISE + 4 * jq]));
            preB[u] = __ldg(reinterpret_cast<const float4*>(&G_GO[gs[rb] * NOISE + 4 * jq]));
        }

        ull acc[4][4];
        #pragma unroll
        for (int u = 0; u < 4; u++) {
            acc[u][0] = pack2(preA[u].x + eb.x, preB[u].x + eb.x);
            acc[u][1] = pack2(preA[u].y + eb.y, preB[u].y + eb.y);
            acc[u][2] = pack2(preA[u].z + eb.z, preB[u].z + eb.z);
            acc[u][3] = pack2(preA[u].w + eb.w, preB[u].w + eb.w);
        }

        const float4* wrow = reinterpret_cast<const float4*>(embW + (size_t)2048 * NOISE) + jq;
        #pragma unroll 4
        for (int k = 0; k < NFEAT; k++) {
            float4 wv = __ldg(wrow + (size_t)k * (NOISE / 4));
            ull wd0 = pack2(wv.x, wv.x);
            ull wd1 = pack2(wv.y, wv.y);
            ull wd2 = pack2(wv.z, wv.z);
            ull wd3 = pack2(wv.w, wv.w);
            ulonglong2 t01 = *reinterpret_cast<const ulonglong2*>(&feat_s[k][8 * w]);
            ulonglong2 t23 = *reinterpret_cast<const ulonglong2*>(&feat_s[k][8 * w + 4]);
            ull tp[4] = {t01.x, t01.y, t23.x, t23.y};
            #pragma unroll
            for (int u = 0; u < 4; u++) {
                acc[u][0] = fma2(wd0, tp[u], acc[u][0]);
                acc[u][1] = fma2(wd1, tp[u], acc[u][1]);
                acc[u][2] = fma2(wd2, tp[u], acc[u][2]);
                acc[u][3] = fma2(wd3, tp[u], acc[u][3]);
            }
        }

        #pragma unroll
        for (int u = 0; u < 4; u++) {
            size_t ra = (size_t)(r0 + 8 * w + 2 * u);
            float4 lo, hi;
            unpack2(acc[u][0], lo.x, hi.x);
            unpack2(acc[u][1], lo.y, hi.y);
            unpack2(acc[u][2], lo.z, hi.z);
            unpack2(acc[u][3], lo.w, hi.w);
            stcs4(out + ra * NOISE + 4 * jq, lo);
            stcs4(out + (ra + 1) * NOISE + 4 * jq, hi);
        }
    }
}

// ============================================================================
extern "C" void kernel_launch(void* const* d_in, const int* in_sizes, int n_in,
                              void* d_out, int out_size) {
    (void)in_sizes; (void)n_in; (void)out_size;
    const int*   gid   = (const int*)  d_in[0];
    const float* chain = (const float*)d_in[1];
    const float* td    = (const float*)d_in[2];
    const float* tx    = (const float*)d_in[3];
    const int*   edges = (const int*)  d_in[4];
    const float* gw    = (const float*)d_in[5];
    const float* gb    = (const float*)d_in[6];
    const float* trigW = (const float*)d_in[7];
    const float* trigb = (const float*)d_in[8];
    const float* embW  = (const float*)d_in[9];
    const float* embb  = (const float*)d_in[10];
    float* out = (float*)d_out;

    // PDL attribute for every secondary in the chain
    cudaLaunchAttribute pattr;
    pattr.id = cudaLaunchAttributeProgrammaticStreamSerialization;
    pattr.val.programmaticStreamSerializationAllowed = 1;

    k_zero<<<SCRATCH_FLOATS / 4 / 256, 256>>>();

    cudaLaunchConfig_t cfg = {};
    cfg.blockDim = dim3(256, 1, 1);
    cfg.stream   = 0;
    cfg.attrs    = &pattr;
    cfg.numAttrs = 1;

    cfg.gridDim = dim3(NGRAPH * ESPLIT, 1, 1);
    cudaLaunchKernelEx(&cfg, k_deg, edges);

    cfg.gridDim = dim3(NGRAPH * ESPLIT, 1, 1);
    cudaLaunchKernelEx(&cfg, k_norm, edges);

    cfg.blockDim = dim3(128, 1, 1);
    cfg.gridDim  = dim3(GK * 8, 1, 1);
    cudaLaunchKernelEx(&cfg, gcn_gemm, embW, gw, gb);

    cfg.gridDim = dim3(B_TOTAL / RROWS, 1, 1);
    cudaLaunchKernelEx(&cfg, noise_main, gid, chain, td, tx, trigW, trigb,
                       embW, embb, out);
}

// round 11
// speedup vs baseline: 1.4338x; 1.2006x over previous
#include <cuda_runtime.h>
#include <cstdint>
#include <cstddef>

#define B_TOTAL 65536
#define NGRAPH  64
#define NNODES  2048
#define NEDGES  16384
#define META    64
#define TXD     8
#define NOISE   128
#define RROWS   32    // rows per block in main kernel
#define NFEAT   41
#define SPAD    36
#define ESPLIT  8
#define GK      128   // gcn_gemm K-splits
#define GROWS   16    // rows per gcn_gemm block

typedef unsigned long long ull;

// Scratch: [deg_part | agg_part | g_go]; partials are [g][sp][node]
#define PART_FLOATS (NGRAPH * ESPLIT * NNODES)          // 1048576
#define SCRATCH_FLOATS (2 * PART_FLOATS + NGRAPH * NOISE)
__device__ float scratch[SCRATCH_FLOATS];
#define DEG_PART (scratch)
#define AGG_PART (scratch + PART_FLOATS)
#define G_GO     (scratch + 2 * PART_FLOATS)

// ---------- PDL ----------
__device__ __forceinline__ void pdl_wait() {
    asm volatile("griddepcontrol.wait;" ::: "memory");
}

// ---------- f32x2 helpers ----------
__device__ __forceinline__ ull pack2(float lo, float hi) {
    ull r; asm("mov.b64 %0, {%1,%2};" : "=l"(r) : "f"(lo), "f"(hi)); return r;
}
__device__ __forceinline__ ull fma2(ull a, ull b, ull c) {
    ull d; asm("fma.rn.f32x2 %0, %1, %2, %3;" : "=l"(d) : "l"(a), "l"(b), "l"(c)); return d;
}
__device__ __forceinline__ void unpack2(ull v, float& lo, float& hi) {
    asm("mov.b64 {%0,%1}, %2;" : "=f"(lo), "=f"(hi) : "l"(v));
}
__device__ __forceinline__ void stcs4(float* p, float4 v) {
    asm volatile("st.global.cs.v4.f32 [%0], {%1,%2,%3,%4};"
                 :: "l"(p), "f"(v.x), "f"(v.y), "f"(v.z), "f"(v.w) : "memory");
}

// ============================================================================
// k_zero: zero ONLY g_go (8192 floats). deg/agg partials are fully overwritten.
// ============================================================================
__global__ __launch_bounds__(256) void k_zero() {
    reinterpret_cast<float4*>(G_GO)[blockIdx.x * 256 + threadIdx.x] =
        make_float4(0.f, 0.f, 0.f, 0.f);
}

// ============================================================================
// k_deg: per-split smem edge count -> dense STG of deg_part. No global atomics.
// 512 blocks = 64 graphs x 8 splits, 8 edges/thread.
// ============================================================================
__global__ __launch_bounds__(256) void k_deg(const int* __restrict__ edges) {
    __shared__ int cnt[NNODES];
    const int g  = blockIdx.x >> 3;
    const int sp = blockIdx.x & 7;
    const int tid = threadIdx.x;

    const int4* dst4 = reinterpret_cast<const int4*>(
        edges + (size_t)g * 2 * NEDGES + NEDGES) + sp * (NEDGES / ESPLIT / 4);
    int4 d0 = __ldg(&dst4[tid]);
    int4 d1 = __ldg(&dst4[256 + tid]);

    #pragma unroll
    for (int i = 0; i < NNODES / 256; i++) cnt[i * 256 + tid] = 0;
    __syncthreads();

    atomicAdd(&cnt[d0.x], 1);
    atomicAdd(&cnt[d0.y], 1);
    atomicAdd(&cnt[d0.z], 1);
    atomicAdd(&cnt[d0.w], 1);
    atomicAdd(&cnt[d1.x], 1);
    atomicAdd(&cnt[d1.y], 1);
    atomicAdd(&cnt[d1.z], 1);
    atomicAdd(&cnt[d1.w], 1);
    __syncthreads();

    pdl_wait();   // keep the chain transitively ordered behind k_zero (cheap)

    float* op = DEG_PART + (size_t)blockIdx.x * NNODES;
    #pragma unroll
    for (int i = 0; i < NNODES / 256; i++)
        op[i * 256 + tid] = (float)cnt[i * 256 + tid];
}

// ============================================================================
// k_norm: sum 8 deg partials -> dinv in smem; smem-accumulate this split's
// norm contributions; dense STG of agg_part. No global atomics.
// ============================================================================
__global__ __launch_bounds__(256) void k_norm(const int* __restrict__ edges) {
    __shared__ float dinv_s[NNODES];
    __shared__ float agg_s[NNODES];
    const int g  = blockIdx.x >> 3;
    const int sp = blockIdx.x & 7;
    const int tid = threadIdx.x;

    const int* base = edges + (size_t)g * 2 * NEDGES;
    const int4* src4 = reinterpret_cast<const int4*>(base) + sp * (NEDGES / ESPLIT / 4);
    const int4* dst4 = reinterpret_cast<const int4*>(base + NEDGES) + sp * (NEDGES / ESPLIT / 4);
    int4 s0 = __ldg(&src4[tid]);
    int4 s1 = __ldg(&src4[256 + tid]);
    int4 d0 = __ldg(&dst4[tid]);
    int4 d1 = __ldg(&dst4[256 + tid]);

    pdl_wait();   // deg_part complete

    const float* dp = DEG_PART + (size_t)g * ESPLIT * NNODES;
    #pragma unroll
    for (int i = 0; i < NNODES / 256; i++) {
        int n = i * 256 + tid;
        float s = 1.0f;   // self loop
        #pragma unroll
        for (int spp = 0; spp < ESPLIT; spp++)
            s += __ldg(&dp[spp * NNODES + n]);
        dinv_s[n] = rsqrtf(s);
        agg_s[n]  = 0.f;
    }
    __syncthreads();

    atomicAdd(&agg_s[d0.x], dinv_s[s0.x] * dinv_s[d0.x]);
    atomicAdd(&agg_s[d0.y], dinv_s[s0.y] * dinv_s[d0.y]);
    atomicAdd(&agg_s[d0.z], dinv_s[s0.z] * dinv_s[d0.z]);
    atomicAdd(&agg_s[d0.w], dinv_s[s0.w] * dinv_s[d0.w]);
    atomicAdd(&agg_s[d1.x], dinv_s[s1.x] * dinv_s[d1.x]);
    atomicAdd(&agg_s[d1.y], dinv_s[s1.y] * dinv_s[d1.y]);
    atomicAdd(&agg_s[d1.z], dinv_s[s1.z] * dinv_s[d1.z]);
    atomicAdd(&agg_s[d1.w], dinv_s[s1.w] * dinv_s[d1.w]);
    __syncthreads();

    float* op = AGG_PART + (size_t)blockIdx.x * NNODES;
    #pragma unroll
    for (int i = 0; i < NNODES / 256; i++)
        op[i * 256 + tid] = agg_s[i * 256 + tid];
}

// ============================================================================
// gcn_gemm: 1024 blocks = 128 K-splits (16 rows) x 8 graph-groups.
// Pass A (pre-wait): wsum. Wait. Sum partials -> agg+dinv^2 -> 16x8 FMA.
// g_go += w * ((AGG + dinv^2) @ embW_slice) + b * colsum(embW_slice)
// ============================================================================
__global__ __launch_bounds__(128) void gcn_gemm(
    const float* __restrict__ embW, const float* __restrict__ gwp,
    const float* __restrict__ gbp)
{
    __shared__ float aggs[8][GROWS];
    const int tid = threadIdx.x;
    const int ks  = blockIdx.x & (GK - 1);
    const int gsp = blockIdx.x >> 7;

    const float* wb = embW + (size_t)ks * GROWS * NOISE + tid;
    float wsum = 0.f;
    #pragma unroll
    for (int n = 0; n < GROWS; n++)
        wsum += __ldg(wb + (size_t)n * NOISE);

    pdl_wait();   // agg_part complete

    {
        int j = tid >> 4, n = tid & (GROWS - 1);   // 128 threads = 8 graphs x 16 nodes
        int g = gsp * 8 + j;
        int node = ks * GROWS + n;
        const float* dp = DEG_PART + (size_t)g * ESPLIT * NNODES + node;
        const float* ap = AGG_PART + (size_t)g * ESPLIT * NNODES + node;
        float dsum = 1.0f, asum = 0.f;
        #pragma unroll
        for (int sp = 0; sp < ESPLIT; sp++) {
            dsum += __ldg(&dp[sp * NNODES]);
            asum += __ldg(&ap[sp * NNODES]);
        }
        float r = rsqrtf(dsum);
        aggs[j][n] = asum + r * r;
    }
    __syncthreads();

    float acc[8] = {0.f, 0.f, 0.f, 0.f, 0.f, 0.f, 0.f, 0.f};
    #pragma unroll
    for (int n = 0; n < GROWS; n++) {
        float wv = __ldg(wb + (size_t)n * NOISE);
        #pragma unroll
        for (int j = 0; j < 8; j++)
            acc[j] = fmaf(aggs[j][n], wv, acc[j]);
    }
    const float w = gwp[0], b = gbp[0];
    const float bterm = b * wsum;
    #pragma unroll
    for (int j = 0; j < 8; j++)
        atomicAdd(&G_GO[(gsp * 8 + j) * NOISE + tid], fmaf(w, acc[j], bterm));
}

// ============================================================================
// noise_main (R8-proven): staging + trig MLP PRE-wait; wait; g_go gather +
// f32x2 output GEMM. 128 threads, 32 rows/block.
// ============================================================================
__global__ __launch_bounds__(128, 5) void noise_main(
    const int*   __restrict__ gid,   const float* __restrict__ chain,
    const float* __restrict__ td,    const float* __restrict__ tx,
    const float* __restrict__ trigW, const float* __restrict__ trigb,
    const float* __restrict__ embW,  const float* __restrict__ embb,
    float* __restrict__ out)
{
    __shared__ __align__(16) float td_s[META][SPAD];
    __shared__ __align__(16) float feat_s[NFEAT][SPAD];
    __shared__ int gs[RROWS];

    const int tid = threadIdx.x;
    const int r0  = blockIdx.x * RROWS;
    const int lane = tid & 31;
    const int w    = tid >> 5;

    {
        const float4* tdg = reinterpret_cast<const float4*>(td + (size_t)r0 * META);
        #pragma unroll
        for (int it = 0; it < 4; it++) {
            int i = it * 128 + tid;
            int r = i >> 4;
            int q = i & 15;
            float4 v = tdg[i];
            float vv[4] = {v.x, v.y, v.z, v.w};
            #pragma unroll
            for (int j = 0; j < 4; j++) {
                int c = ((q >> 1) + j) & 3;
                td_s[4 * q + c][r] = vv[c];
            }
        }
        if (tid < 64) {
            const float4* txg = reinterpret_cast<const float4*>(tx + (size_t)r0 * TXD);
            int r = tid >> 1, q = tid & 1;
            float4 v = txg[tid];
            feat_s[33 + 4 * q + 0][r] = v.x;
            feat_s[33 + 4 * q + 1][r] = v.y;
            feat_s[33 + 4 * q + 2][r] = v.z;
            feat_s[33 + 4 * q + 3][r] = v.w;
        }
        if (tid < RROWS) {
            feat_s[0][tid] = chain[r0 + tid];
            gs[tid] = gid[r0 + tid];
        }
    }
    __syncthreads();

    {
        const int k = lane;
        float tb = __ldg(&trigb[k]);
        ull acc0 = pack2(tb, tb), acc1 = acc0, acc2 = acc0, acc3 = acc0;
        #pragma unroll 8
        for (int m = 0; m < META; m++) {
            float wv = __ldg(&trigW[m * 32 + k]);
            ull wd = pack2(wv, wv);
            ulonglong2 t01 = *reinterpret_cast<const ulonglong2*>(&td_s[m][8 * w]);
            ulonglong2 t23 = *reinterpret_cast<const ulonglong2*>(&td_s[m][8 * w + 4]);
            acc0 = fma2(wd, t01.x, acc0);
            acc1 = fma2(wd, t01.y, acc1);
            acc2 = fma2(wd, t23.x, acc2);
            acc3 = fma2(wd, t23.y, acc3);
        }
        float a, b2;
        unpack2(acc0, a, b2);
        *reinterpret_cast<ull*>(&feat_s[1 + k][8 * w + 0]) = pack2(fmaxf(a, 0.f), fmaxf(b2, 0.f));
        unpack2(acc1, a, b2);
        *reinterpret_cast<ull*>(&feat_s[1 + k][8 * w + 2]) = pack2(fmaxf(a, 0.f), fmaxf(b2, 0.f));
        unpack2(acc2, a, b2);
        *reinterpret_cast<ull*>(&feat_s[1 + k][8 * w + 4]) = pack2(fmaxf(a, 0.f), fmaxf(b2, 0.f));
        unpack2(acc3, a, b2);
        *reinterpret_cast<ull*>(&feat_s[1 + k][8 * w + 6]) = pack2(fmaxf(a, 0.f), fmaxf(b2, 0.f));
    }
    __syncthreads();

    pdl_wait();   // g_go complete

    {
        const int jq = lane;
        const float4 eb = __ldg(reinterpret_cast<const float4*>(&embb[4 * jq]));

        float4 preA[4], preB[4];
        #pragma unroll
        for (int u = 0; u < 4; u++) {
            int ra = 8 * w + 2 * u, rb = ra + 1;
            preA[u] = __ldg(reinterpret_cast<const float4*>(&G_GO[gs[ra] * NOISE + 4 * jq]));
            preB[u] = __ldg(reinterpret_cast<const float4*>(&G_GO[gs[rb] * NOISE + 4 * jq]));
        }

        ull acc[4][4];
        #pragma unroll
        for (int u = 0; u < 4; u++) {
            acc[u][0] = pack2(preA[u].x + eb.x, preB[u].x + eb.x);
            acc[u][1] = pack2(preA[u].y + eb.y, preB[u].y + eb.y);
            acc[u][2] = pack2(preA[u].z + eb.z, preB[u].z + eb.z);
            acc[u][3] = pack2(preA[u].w + eb.w, preB[u].w + eb.w);
        }

        const float4* wrow = reinterpret_cast<const float4*>(embW + (size_t)2048 * NOISE) + jq;
        #pragma unroll 4
        for (int k = 0; k < NFEAT; k++) {
            float4 wv = __ldg(wrow + (size_t)k * (NOISE / 4));
            ull wd0 = pack2(wv.x, wv.x);
            ull wd1 = pack2(wv.y, wv.y);
            ull wd2 = pack2(wv.z, wv.z);
            ull wd3 = pack2(wv.w, wv.w);
            ulonglong2 t01 = *reinterpret_cast<const ulonglong2*>(&feat_s[k][8 * w]);
            ulonglong2 t23 = *reinterpret_cast<const ulonglong2*>(&feat_s[k][8 * w + 4]);
            ull tp[4] = {t01.x, t01.y, t23.x, t23.y};
            #pragma unroll
            for (int u = 0; u < 4; u++) {
                acc[u][0] = fma2(wd0, tp[u], acc[u][0]);
                acc[u][1] = fma2(wd1, tp[u], acc[u][1]);
                acc[u][2] = fma2(wd2, tp[u], acc[u][2]);
                acc[u][3] = fma2(wd3, tp[u], acc[u][3]);
            }
        }

        #pragma unroll
        for (int u = 0; u < 4; u++) {
            size_t ra = (size_t)(r0 + 8 * w + 2 * u);
            float4 lo, hi;
            unpack2(acc[u][0], lo.x, hi.x);
            unpack2(acc[u][1], lo.y, hi.y);
            unpack2(acc[u][2], lo.z, hi.z);
            unpack2(acc[u][3], lo.w, hi.w);
            stcs4(out + ra * NOISE + 4 * jq, lo);
            stcs4(out + (ra + 1) * NOISE + 4 * jq, hi);
        }
    }
}

// ============================================================================
extern "C" void kernel_launch(void* const* d_in, const int* in_sizes, int n_in,
                              void* d_out, int out_size) {
    (void)in_sizes; (void)n_in; (void)out_size;
    const int*   gid   = (const int*)  d_in[0];
    const float* chain = (const float*)d_in[1];
    const float* td    = (const float*)d_in[2];
    const float* tx    = (const float*)d_in[3];
    const int*   edges = (const int*)  d_in[4];
    const float* gw    = (const float*)d_in[5];
    const float* gb    = (const float*)d_in[6];
    const float* trigW = (const float*)d_in[7];
    const float* trigb = (const float*)d_in[8];
    const float* embW  = (const float*)d_in[9];
    const float* embb  = (const float*)d_in[10];
    float* out = (float*)d_out;

    cudaLaunchAttribute pattr;
    pattr.id = cudaLaunchAttributeProgrammaticStreamSerialization;
    pattr.val.programmaticStreamSerializationAllowed = 1;

    k_zero<<<NGRAPH * NOISE / 4 / 256, 256>>>();

    cudaLaunchConfig_t cfg = {};
    cfg.blockDim = dim3(256, 1, 1);
    cfg.stream   = 0;
    cfg.attrs    = &pattr;
    cfg.numAttrs = 1;

    cfg.gridDim = dim3(NGRAPH * ESPLIT, 1, 1);
    cudaLaunchKernelEx(&cfg, k_deg, edges);

    cfg.gridDim = dim3(NGRAPH * ESPLIT, 1, 1);
    cudaLaunchKernelEx(&cfg, k_norm, edges);

    cfg.blockDim = dim3(128, 1, 1);
    cfg.gridDim  = dim3(GK * 8, 1, 1);
    cudaLaunchKernelEx(&cfg, gcn_gemm, embW, gw, gb);

    cfg.gridDim = dim3(B_TOTAL / RROWS, 1, 1);
    cudaLaunchKernelEx(&cfg, noise_main, gid, chain, td, tx, trigW, trigb,
                       embW, embb, out);
}

// round 12
// speedup vs baseline: 1.4946x; 1.0424x over previous
#include <cuda_runtime.h>
#include <cstdint>
#include <cstddef>

#define B_TOTAL 65536
#define NGRAPH  64
#define NNODES  2048
#define NEDGES  16384
#define META    64
#define TXD     8
#define NOISE   128
#define RROWS   32    // rows per block in main kernel
#define NFEAT   41
#define SPAD    36
#define ESPLIT  8
#define GK      128   // gcn_gemm K-splits
#define GROWS   16    // rows per gcn_gemm block

typedef unsigned long long ull;

// Scratch: [deg_part | agg_part | g_go]; partials are [g][sp][node]
#define PART_FLOATS (NGRAPH * ESPLIT * NNODES)          // 1048576
#define SCRATCH_FLOATS (2 * PART_FLOATS + NGRAPH * NOISE)
__device__ float scratch[SCRATCH_FLOATS];
#define DEG_PART (scratch)
#define AGG_PART (scratch + PART_FLOATS)
#define G_GO     (scratch + 2 * PART_FLOATS)

// ---------- PDL ----------
__device__ __forceinline__ void pdl_wait() {
    asm volatile("griddepcontrol.wait;" ::: "memory");
}

// ---------- f32x2 helpers ----------
__device__ __forceinline__ ull pack2(float lo, float hi) {
    ull r; asm("mov.b64 %0, {%1,%2};" : "=l"(r) : "f"(lo), "f"(hi)); return r;
}
__device__ __forceinline__ ull fma2(ull a, ull b, ull c) {
    ull d; asm("fma.rn.f32x2 %0, %1, %2, %3;" : "=l"(d) : "l"(a), "l"(b), "l"(c)); return d;
}
__device__ __forceinline__ void unpack2(ull v, float& lo, float& hi) {
    asm("mov.b64 {%0,%1}, %2;" : "=f"(lo), "=f"(hi) : "l"(v));
}
__device__ __forceinline__ void stcs4(float* p, float4 v) {
    asm volatile("st.global.cs.v4.f32 [%0], {%1,%2,%3,%4};"
                 :: "l"(p), "f"(v.x), "f"(v.y), "f"(v.z), "f"(v.w) : "memory");
}

// ============================================================================
// k_deg (chain head, no wait): per-split smem edge count -> dense STG of
// deg_part. Split-0 blocks also zero g_go (consumed 2 grids later).
// 512 blocks = 64 graphs x 8 splits, 8 edges/thread.
// ============================================================================
__global__ __launch_bounds__(256) void k_deg(const int* __restrict__ edges) {
    __shared__ int cnt[NNODES];
    const int g  = blockIdx.x >> 3;
    const int sp = blockIdx.x & 7;
    const int tid = threadIdx.x;

    const int4* dst4 = reinterpret_cast<const int4*>(
        edges + (size_t)g * 2 * NEDGES + NEDGES) + sp * (NEDGES / ESPLIT / 4);
    int4 d0 = __ldg(&dst4[tid]);
    int4 d1 = __ldg(&dst4[256 + tid]);

    if (sp == 0 && tid < NOISE) G_GO[g * NOISE + tid] = 0.f;

    #pragma unroll
    for (int i = 0; i < NNODES / 256; i++) cnt[i * 256 + tid] = 0;
    __syncthreads();

    atomicAdd(&cnt[d0.x], 1);
    atomicAdd(&cnt[d0.y], 1);
    atomicAdd(&cnt[d0.z], 1);
    atomicAdd(&cnt[d0.w], 1);
    atomicAdd(&cnt[d1.x], 1);
    atomicAdd(&cnt[d1.y], 1);
    atomicAdd(&cnt[d1.z], 1);
    atomicAdd(&cnt[d1.w], 1);
    __syncthreads();

    float* op = DEG_PART + (size_t)blockIdx.x * NNODES;
    #pragma unroll
    for (int i = 0; i < NNODES / 256; i++)
        op[i * 256 + tid] = (float)cnt[i * 256 + tid];
}

// ============================================================================
// k_norm: edge loads (prologue) -> wait -> sum deg partials -> dinv in smem ->
// smem-accumulate split's norm contributions -> dense STG of agg_part.
// ============================================================================
__global__ __launch_bounds__(256) void k_norm(const int* __restrict__ edges) {
    __shared__ float dinv_s[NNODES];
    __shared__ float agg_s[NNODES];
    const int g  = blockIdx.x >> 3;
    const int sp = blockIdx.x & 7;
    const int tid = threadIdx.x;

    const int* base = edges + (size_t)g * 2 * NEDGES;
    const int4* src4 = reinterpret_cast<const int4*>(base) + sp * (NEDGES / ESPLIT / 4);
    const int4* dst4 = reinterpret_cast<const int4*>(base + NEDGES) + sp * (NEDGES / ESPLIT / 4);
    int4 s0 = __ldg(&src4[tid]);
    int4 s1 = __ldg(&src4[256 + tid]);
    int4 d0 = __ldg(&dst4[tid]);
    int4 d1 = __ldg(&dst4[256 + tid]);

    pdl_wait();   // deg_part complete

    const float* dp = DEG_PART + (size_t)g * ESPLIT * NNODES;
    #pragma unroll
    for (int i = 0; i < NNODES / 256; i++) {
        int n = i * 256 + tid;
        float s = 1.0f;   // self loop
        #pragma unroll
        for (int spp = 0; spp < ESPLIT; spp++)
            s += __ldg(&dp[spp * NNODES + n]);
        dinv_s[n] = rsqrtf(s);
        agg_s[n]  = 0.f;
    }
    __syncthreads();

    atomicAdd(&agg_s[d0.x], dinv_s[s0.x] * dinv_s[d0.x]);
    atomicAdd(&agg_s[d0.y], dinv_s[s0.y] * dinv_s[d0.y]);
    atomicAdd(&agg_s[d0.z], dinv_s[s0.z] * dinv_s[d0.z]);
    atomicAdd(&agg_s[d0.w], dinv_s[s0.w] * dinv_s[d0.w]);
    atomicAdd(&agg_s[d1.x], dinv_s[s1.x] * dinv_s[d1.x]);
    atomicAdd(&agg_s[d1.y], dinv_s[s1.y] * dinv_s[d1.y]);
    atomicAdd(&agg_s[d1.z], dinv_s[s1.z] * dinv_s[d1.z]);
    atomicAdd(&agg_s[d1.w], dinv_s[s1.w] * dinv_s[d1.w]);
    __syncthreads();

    float* op = AGG_PART + (size_t)blockIdx.x * NNODES;
    #pragma unroll
    for (int i = 0; i < NNODES / 256; i++)
        op[i * 256 + tid] = agg_s[i * 256 + tid];
}

// ============================================================================
// gcn_gemm: 1024 blocks = 128 K-splits (16 rows) x 8 graph-groups.
// Pass A (pre-wait): wsum. Wait. Sum partials -> agg+dinv^2 -> 16x8 FMA.
// g_go += w * ((AGG + dinv^2) @ embW_slice) + b * colsum(embW_slice)
// ============================================================================
__global__ __launch_bounds__(128) void gcn_gemm(
    const float* __restrict__ embW, const float* __restrict__ gwp,
    const float* __restrict__ gbp)
{
    __shared__ float aggs[8][GROWS];
    const int tid = threadIdx.x;
    const int ks  = blockIdx.x & (GK - 1);
    const int gsp = blockIdx.x >> 7;

    const float* wb = embW + (size_t)ks * GROWS * NOISE + tid;
    float wsum = 0.f;
    #pragma unroll
    for (int n = 0; n < GROWS; n++)
        wsum += __ldg(wb + (size_t)n * NOISE);

    pdl_wait();   // agg_part complete

    {
        int j = tid >> 4, n = tid & (GROWS - 1);   // 128 threads = 8 graphs x 16 nodes
        int g = gsp * 8 + j;
        int node = ks * GROWS + n;
        const float* dp = DEG_PART + (size_t)g * ESPLIT * NNODES + node;
        const float* ap = AGG_PART + (size_t)g * ESPLIT * NNODES + node;
        float dsum = 1.0f, asum = 0.f;
        #pragma unroll
        for (int sp = 0; sp < ESPLIT; sp++) {
            dsum += __ldg(&dp[sp * NNODES]);
            asum += __ldg(&ap[sp * NNODES]);
        }
        float r = rsqrtf(dsum);
        aggs[j][n] = asum + r * r;
    }
    __syncthreads();

    float acc[8] = {0.f, 0.f, 0.f, 0.f, 0.f, 0.f, 0.f, 0.f};
    #pragma unroll
    for (int n = 0; n < GROWS; n++) {
        float wv = __ldg(wb + (size_t)n * NOISE);
        #pragma unroll
        for (int j = 0; j < 8; j++)
            acc[j] = fmaf(aggs[j][n], wv, acc[j]);
    }
    const float w = gwp[0], b = gbp[0];
    const float bterm = b * wsum;
    #pragma unroll
    for (int j = 0; j < 8; j++)
        atomicAdd(&G_GO[(gsp * 8 + j) * NOISE + tid], fmaf(w, acc[j], bterm));
}

// ============================================================================
// noise_main: staging + trig MLP PRE-wait; wait; g_go gather fused into acc
// init (regs freed); f32x2 output GEMM. 128 threads, 32 rows, 6 blocks/SM.
// ============================================================================
__global__ __launch_bounds__(128, 6) void noise_main(
    const int*   __restrict__ gid,   const float* __restrict__ chain,
    const float* __restrict__ td,    const float* __restrict__ tx,
    const float* __restrict__ trigW, const float* __restrict__ trigb,
    const float* __restrict__ embW,  const float* __restrict__ embb,
    float* __restrict__ out)
{
    __shared__ __align__(16) float td_s[META][SPAD];
    __shared__ __align__(16) float feat_s[NFEAT][SPAD];
    __shared__ int gs[RROWS];

    const int tid = threadIdx.x;
    const int r0  = blockIdx.x * RROWS;
    const int lane = tid & 31;
    const int w    = tid >> 5;

    {
        const float4* tdg = reinterpret_cast<const float4*>(td + (size_t)r0 * META);
        #pragma unroll
        for (int it = 0; it < 4; it++) {
            int i = it * 128 + tid;
            int r = i >> 4;
            int q = i & 15;
            float4 v = tdg[i];
            float vv[4] = {v.x, v.y, v.z, v.w};
            #pragma unroll
            for (int j = 0; j < 4; j++) {
                int c = ((q >> 1) + j) & 3;
                td_s[4 * q + c][r] = vv[c];
            }
        }
        if (tid < 64) {
            const float4* txg = reinterpret_cast<const float4*>(tx + (size_t)r0 * TXD);
            int r = tid >> 1, q = tid & 1;
            float4 v = txg[tid];
            feat_s[33 + 4 * q + 0][r] = v.x;
            feat_s[33 + 4 * q + 1][r] = v.y;
            feat_s[33 + 4 * q + 2][r] = v.z;
            feat_s[33 + 4 * q + 3][r] = v.w;
        }
        if (tid < RROWS) {
            feat_s[0][tid] = chain[r0 + tid];
            gs[tid] = gid[r0 + tid];
        }
    }
    __syncthreads();

    {
        const int k = lane;
        float tb = __ldg(&trigb[k]);
        ull acc0 = pack2(tb, tb), acc1 = acc0, acc2 = acc0, acc3 = acc0;
        #pragma unroll 8
        for (int m = 0; m < META; m++) {
            float wv = __ldg(&trigW[m * 32 + k]);
            ull wd = pack2(wv, wv);
            ulonglong2 t01 = *reinterpret_cast<const ulonglong2*>(&td_s[m][8 * w]);
            ulonglong2 t23 = *reinterpret_cast<const ulonglong2*>(&td_s[m][8 * w + 4]);
            acc0 = fma2(wd, t01.x, acc0);
            acc1 = fma2(wd, t01.y, acc1);
            acc2 = fma2(wd, t23.x, acc2);
            acc3 = fma2(wd, t23.y, acc3);
        }
        float a, b2;
        unpack2(acc0, a, b2);
        *reinterpret_cast<ull*>(&feat_s[1 + k][8 * w + 0]) = pack2(fmaxf(a, 0.f), fmaxf(b2, 0.f));
        unpack2(acc1, a, b2);
        *reinterpret_cast<ull*>(&feat_s[1 + k][8 * w + 2]) = pack2(fmaxf(a, 0.f), fmaxf(b2, 0.f));
        unpack2(acc2, a, b2);
        *reinterpret_cast<ull*>(&feat_s[1 + k][8 * w + 4]) = pack2(fmaxf(a, 0.f), fmaxf(b2, 0.f));
        unpack2(acc3, a, b2);
        *reinterpret_cast<ull*>(&feat_s[1 + k][8 * w + 6]) = pack2(fmaxf(a, 0.f), fmaxf(b2, 0.f));
    }
    __syncthreads();

    pdl_wait();   // g_go complete

    {
        const int jq = lane;
        const float4 eb = __ldg(reinterpret_cast<const float4*>(&embb[4 * jq]));

        // gather + acc init fused (no separate prefetch arrays -> fewer regs)
        ull acc[4][4];
        #pragma unroll
        for (int u = 0; u < 4; u++) {
            int ra = 8 * w + 2 * u, rb = ra + 1;
            float4 ga = __ldg(reinterpret_cast<const float4*>(&G_GO[gs[ra] * NOISE + 4 * jq]));
            float4 gb = __ldg(reinterpret_cast<const float4*>(&G_GO[gs[rb] * NOISE + 4 * jq]));
            acc[u][0] = pack2(ga.x + eb.x, gb.x + eb.x);
            acc[u][1] = pack2(ga.y + eb.y, gb.y + eb.y);
            acc[u][2] = pack2(ga.z + eb.z, gb.z + eb.z);
            acc[u][3] = pack2(ga.w + eb.w, gb.w + eb.w);
        }

        const float4* wrow = reinterpret_cast<const float4*>(embW + (size_t)2048 * NOISE) + jq;
        #pragma unroll 4
        for (int k = 0; k < NFEAT; k++) {
            float4 wv = __ldg(wrow + (size_t)k * (NOISE / 4));
            ull wd0 = pack2(wv.x, wv.x);
            ull wd1 = pack2(wv.y, wv.y);
            ull wd2 = pack2(wv.z, wv.z);
            ull wd3 = pack2(wv.w, wv.w);
            ulonglong2 t01 = *reinterpret_cast<const ulonglong2*>(&feat_s[k][8 * w]);
            ulonglong2 t23 = *reinterpret_cast<const ulonglong2*>(&feat_s[k][8 * w + 4]);
            ull tp[4] = {t01.x, t01.y, t23.x, t23.y};
            #pragma unroll
            for (int u = 0; u < 4; u++) {
                acc[u][0] = fma2(wd0, tp[u], acc[u][0]);
                acc[u][1] = fma2(wd1, tp[u], acc[u][1]);
                acc[u][2] = fma2(wd2, tp[u], acc[u][2]);
                acc[u][3] = fma2(wd3, tp[u], acc[u][3]);
            }
        }

        #pragma unroll
        for (int u = 0; u < 4; u++) {
            size_t ra = (size_t)(r0 + 8 * w + 2 * u);
            float4 lo, hi;
            unpack2(acc[u][0], lo.x, hi.x);
            unpack2(acc[u][1], lo.y, hi.y);
            unpack2(acc[u][2], lo.z, hi.z);
            unpack2(acc[u][3], lo.w, hi.w);
            stcs4(out + ra * NOISE + 4 * jq, lo);
            stcs4(out + (ra + 1) * NOISE + 4 * jq, hi);
        }
    }
}

// ============================================================================
extern "C" void kernel_launch(void* const* d_in, const int* in_sizes, int n_in,
                              void* d_out, int out_size) {
    (void)in_sizes; (void)n_in; (void)out_size;
    const int*   gid   = (const int*)  d_in[0];
    const float* chain = (const float*)d_in[1];
    const float* td    = (const float*)d_in[2];
    const float* tx    = (const float*)d_in[3];
    const int*   edges = (const int*)  d_in[4];
    const float* gw    = (const float*)d_in[5];
    const float* gb    = (const float*)d_in[6];
    const float* trigW = (const float*)d_in[7];
    const float* trigb = (const float*)d_in[8];
    const float* embW  = (const float*)d_in[9];
    const float* embb  = (const float*)d_in[10];
    float* out = (float*)d_out;

    cudaLaunchAttribute pattr;
    pattr.id = cudaLaunchAttributeProgrammaticStreamSerialization;
    pattr.val.programmaticStreamSerializationAllowed = 1;

    // chain head: plain launch, no wait inside
    k_deg<<<NGRAPH * ESPLIT, 256>>>(edges);

    cudaLaunchConfig_t cfg = {};
    cfg.blockDim = dim3(256, 1, 1);
    cfg.stream   = 0;
    cfg.attrs    = &pattr;
    cfg.numAttrs = 1;

    cfg.gridDim = dim3(NGRAPH * ESPLIT, 1, 1);
    cudaLaunchKernelEx(&cfg, k_norm, edges);

    cfg.blockDim = dim3(128, 1, 1);
    cfg.gridDim  = dim3(GK * 8, 1, 1);
    cudaLaunchKernelEx(&cfg, gcn_gemm, embW, gw, gb);

    cfg.gridDim = dim3(B_TOTAL / RROWS, 1, 1);
    cudaLaunchKernelEx(&cfg, noise_main, gid, chain, td, tx, trigW, trigb,
                       embW, embb, out);
}